// round 1
// baseline (speedup 1.0000x reference)
#include <cuda_runtime.h>

#define Bb 32
#define Cc 3
#define Hh 512
#define Ww 512
#define NPIX (Hh*Ww)
#define CUTSZ 128
#define PARTS 8

// Scratch (no allocations allowed)
__device__ float g_part[Bb*Cc*PARTS];
__device__ float g_mean[Bb*Cc];

// ---------------------------------------------------------------------------
// Kernel 1a: per-(b,c) partial sums of clip(img + bf, -1, 1)
// 768 blocks x 256 threads; each block sums 32768 contiguous floats (float4).
// ---------------------------------------------------------------------------
__global__ void __launch_bounds__(256) mean_partial(const float* __restrict__ img,
                                                    const float* __restrict__ u_bright)
{
    int bc   = blockIdx.x / PARTS;
    int part = blockIdx.x % PARTS;
    int b    = bc / Cc;
    float bf = (u_bright[b] * 2.0f - 1.0f) * 0.2f;

    const float4* p = (const float4*)(img + (size_t)bc * NPIX + (size_t)part * (NPIX / PARTS));
    int t = threadIdx.x;
    float s = 0.0f;
#pragma unroll
    for (int i = 0; i < 32; i++) {
        float4 v = p[t + i * 256];
        s += fminf(fmaxf(v.x + bf, -1.0f), 1.0f);
        s += fminf(fmaxf(v.y + bf, -1.0f), 1.0f);
        s += fminf(fmaxf(v.z + bf, -1.0f), 1.0f);
        s += fminf(fmaxf(v.w + bf, -1.0f), 1.0f);
    }
    __shared__ float sh[256];
    sh[t] = s;
    __syncthreads();
    for (int o = 128; o > 0; o >>= 1) {
        if (t < o) sh[t] += sh[t + o];
        __syncthreads();
    }
    if (t == 0) g_part[blockIdx.x] = sh[0];
}

// ---------------------------------------------------------------------------
// Kernel 1b: finalize means
// ---------------------------------------------------------------------------
__global__ void mean_final()
{
    int i = threadIdx.x;
    if (i < Bb * Cc) {
        float s = 0.0f;
#pragma unroll
        for (int k = 0; k < PARTS; k++) s += g_part[i * PARTS + k];
        g_mean[i] = s * (1.0f / (float)NPIX);
    }
}

// ---------------------------------------------------------------------------
// Per-corner color transform: brightness -> contrast -> HSV adjust -> RGB
// ---------------------------------------------------------------------------
__device__ __forceinline__ float3 color_xform(float cr, float cg, float cb,
                                              float bf, float cf,
                                              float mr, float mg, float mb2,
                                              float dh, float sf)
{
    // brightness + clip
    cr = fminf(fmaxf(cr + bf, -1.0f), 1.0f);
    cg = fminf(fmaxf(cg + bf, -1.0f), 1.0f);
    cb = fminf(fmaxf(cb + bf, -1.0f), 1.0f);
    // contrast + clip
    cr = fminf(fmaxf((cr - mr)  * cf + mr,  -1.0f), 1.0f);
    cg = fminf(fmaxf((cg - mg)  * cf + mg,  -1.0f), 1.0f);
    cb = fminf(fmaxf((cb - mb2) * cf + mb2, -1.0f), 1.0f);

    // rgb -> hsv
    float mx = fmaxf(cr, fmaxf(cg, cb));
    float mn = fminf(cr, fminf(cg, cb));
    float d  = mx - mn;
    float invd = (d == 0.0f) ? 1.0f : __fdividef(1.0f, d);

    // hue in [0,1]; mod-360 only ever wraps the hr<0 case
    float tr = (cg - cb) * invd;                      // in [-1, 1]
    float hr = tr * (1.0f / 6.0f);
    hr = (tr < 0.0f) ? hr + 1.0f : hr;
    float hg = fmaf((cb - cr) * invd, 1.0f / 6.0f, 2.0f / 6.0f);
    float hb = fmaf((cr - cg) * invd, 1.0f / 6.0f, 4.0f / 6.0f);
    float hch = (mx == cb) ? hb : ((mx == cg) ? hg : ((mx == cr) ? hr : 0.0f));

    // saturation fold: c = v * clip(s*sf,0,1) = (mx>0) ? min(d*sf, mx) : 0
    float c = (mx > 0.0f) ? fminf(d * sf, mx) : 0.0f;

    // hue shift + clip
    float hp = fminf(fmaxf(hch + dh, 0.0f), 1.0f);

    // hsv -> rgb
    float t6 = hp * 6.0f;                             // [0, 6]; 6 -> gray (all segs false)
    float m2 = t6 - 2.0f * floorf(t6 * 0.5f);
    float xv = c * (1.0f - fabsf(m2 - 1.0f));
    float m  = mx - c;
    int seg  = (int)t6;
    float rr = (seg == 0 || seg == 5) ? c : ((seg == 1 || seg == 4) ? xv : 0.0f);
    float gg = (seg == 1 || seg == 2) ? c : ((seg == 0 || seg == 3) ? xv : 0.0f);
    float bb = (seg == 3 || seg == 4) ? c : ((seg == 2 || seg == 5) ? xv : 0.0f);
    return make_float3(rr + m, gg + m, bb + m);
}

// ---------------------------------------------------------------------------
// Kernel 2: fused rotate-resample + color pipeline + noise + cutout
// One thread per (b,h,w); writes all 3 channels.
// ---------------------------------------------------------------------------
__global__ void __launch_bounds__(256) aug_kernel(
    const float* __restrict__ img,
    const float* __restrict__ u_bright,
    const float* __restrict__ u_contrast,
    const float* __restrict__ u_hue,
    const float* __restrict__ u_sat,
    const float* __restrict__ u_angle,
    const float* __restrict__ noise,
    const int*   __restrict__ cutout_xy,
    const int*   __restrict__ cutout_apply,
    float*       __restrict__ out)
{
    int w = blockIdx.x * 32 + threadIdx.x;
    int h = blockIdx.y * 8  + threadIdx.y;
    int b = blockIdx.z;

    // Per-batch params (uniform per block -> uniform loads, cached)
    float bf  = (u_bright[b]   * 2.0f - 1.0f) * 0.2f;
    float cf  = 1.0f + (u_contrast[b] * 2.0f - 1.0f) * 0.2f;
    float dh  = (u_hue[b]      * 2.0f - 1.0f) * 0.1f;
    float sf  = 1.0f + (u_sat[b]      * 2.0f - 1.0f) * 0.2f;
    float ang = (u_angle[b]    * 2.0f - 1.0f) * 0.17453292519943295f; // 10 deg in rad
    float sa, ca;
    sincosf(ang, &sa, &ca);
    float mr  = g_mean[b * 3 + 0];
    float mg  = g_mean[b * 3 + 1];
    float mb2 = g_mean[b * 3 + 2];

    // rotation grid (matches linspace(-1,1,512) and align_corners=False)
    float xx = fmaf((float)w, 2.0f / 511.0f, -1.0f);
    float yy = fmaf((float)h, 2.0f / 511.0f, -1.0f);
    float gx = ca * xx - sa * yy;
    float gy = sa * xx + ca * yy;
    float gxp = (gx + 1.0f) * 256.0f - 0.5f;
    float gyp = (gy + 1.0f) * 256.0f - 0.5f;
    float x0f = floorf(gxp), y0f = floorf(gyp);
    float wx = gxp - x0f, wy = gyp - y0f;
    int x0 = (int)x0f, y0 = (int)y0f;

    float accr = 0.0f, accg = 0.0f, accb = 0.0f;
    const float* base = img + (size_t)b * Cc * NPIX;

#pragma unroll
    for (int cyi = 0; cyi < 2; cyi++) {
        int yi = y0 + cyi;
        if (yi < 0 || yi >= Hh) continue;
        float wyc = cyi ? wy : (1.0f - wy);
        int row = Hh - 1 - yi;                         // vertical flip
#pragma unroll
        for (int cxi = 0; cxi < 2; cxi++) {
            int xi = x0 + cxi;
            if (xi < 0 || xi >= Ww) continue;
            float wgt = wyc * (cxi ? wx : (1.0f - wx));
            int off = row * Ww + xi;
            float r  = __ldg(base + off);
            float g  = __ldg(base + NPIX + off);
            float bl = __ldg(base + 2 * NPIX + off);
            float3 c = color_xform(r, g, bl, bf, cf, mr, mg, mb2, dh, sf);
            accr = fmaf(c.x, wgt, accr);
            accg = fmaf(c.y, wgt, accg);
            accb = fmaf(c.z, wgt, accb);
        }
    }

    // noise + clip
    size_t o = (size_t)b * Cc * NPIX + (size_t)h * Ww + w;
    float nr = noise[o];
    float ng = noise[o + NPIX];
    float nb = noise[o + 2 * NPIX];
    accr = fminf(fmaxf(fmaf(nr, 0.05f, accr), -1.0f), 1.0f);
    accg = fminf(fmaxf(fmaf(ng, 0.05f, accg), -1.0f), 1.0f);
    accb = fminf(fmaxf(fmaf(nb, 0.05f, accb), -1.0f), 1.0f);

    // cutout
    int cx = cutout_xy[b * 2 + 0];
    int cy = cutout_xy[b * 2 + 1];
    bool cut = (cutout_apply[b] != 0) &&
               (h >= cy) && (h < cy + CUTSZ) &&
               (w >= cx) && (w < cx + CUTSZ);
    if (cut) { accr = 0.0f; accg = 0.0f; accb = 0.0f; }

    out[o]            = accr;
    out[o + NPIX]     = accg;
    out[o + 2 * NPIX] = accb;
}

// ---------------------------------------------------------------------------
extern "C" void kernel_launch(void* const* d_in, const int* in_sizes, int n_in,
                              void* d_out, int out_size)
{
    const float* img        = (const float*)d_in[0];
    const float* u_bright   = (const float*)d_in[1];
    const float* u_contrast = (const float*)d_in[2];
    const float* u_hue      = (const float*)d_in[3];
    const float* u_sat      = (const float*)d_in[4];
    const float* u_angle    = (const float*)d_in[5];
    const float* noise      = (const float*)d_in[6];
    const int*   cutout_xy  = (const int*)d_in[7];
    const int*   cutout_ap  = (const int*)d_in[8];
    float* out = (float*)d_out;

    mean_partial<<<Bb * Cc * PARTS, 256>>>(img, u_bright);
    mean_final<<<1, 128>>>();

    dim3 blk(32, 8, 1);
    dim3 grd(Ww / 32, Hh / 8, Bb);
    aug_kernel<<<grd, blk>>>(img, u_bright, u_contrast, u_hue, u_sat, u_angle,
                             noise, cutout_xy, cutout_ap, out);
}

// round 2
// speedup vs baseline: 1.3732x; 1.3732x over previous
#include <cuda_runtime.h>

#define Bb 32
#define Cc 3
#define Hh 512
#define Ww 512
#define NPIX (Hh*Ww)
#define CUTSZ 128
#define PARTS 8

#define TW 64
#define TH 64
#define SSTR 76               // smem tile stride (max bbox extent = 75)
#define SPLANE (SSTR*SSTR)    // 5776 floats per channel plane
#define AUG_SMEM (3*SPLANE*4) // 69312 bytes

// Scratch (no allocations allowed)
__device__ float g_part[Bb*Cc*PARTS];
__device__ float g_mean[Bb*Cc];

// ---------------------------------------------------------------------------
// Kernel 1a: per-(b,c) partial sums of clip(img + bf, -1, 1)
// ---------------------------------------------------------------------------
__global__ void __launch_bounds__(256) mean_partial(const float* __restrict__ img,
                                                    const float* __restrict__ u_bright)
{
    int bc   = blockIdx.x / PARTS;
    int part = blockIdx.x % PARTS;
    int b    = bc / Cc;
    float bf = (u_bright[b] * 2.0f - 1.0f) * 0.2f;

    const float4* p = (const float4*)(img + (size_t)bc * NPIX + (size_t)part * (NPIX / PARTS));
    int t = threadIdx.x;
    float s0 = 0.0f, s1 = 0.0f, s2 = 0.0f, s3 = 0.0f;
#pragma unroll
    for (int i = 0; i < 32; i += 4) {
        float4 v0 = p[t + (i + 0) * 256];
        float4 v1 = p[t + (i + 1) * 256];
        float4 v2 = p[t + (i + 2) * 256];
        float4 v3 = p[t + (i + 3) * 256];
        s0 += fminf(fmaxf(v0.x + bf, -1.0f), 1.0f) + fminf(fmaxf(v0.y + bf, -1.0f), 1.0f)
            + fminf(fmaxf(v0.z + bf, -1.0f), 1.0f) + fminf(fmaxf(v0.w + bf, -1.0f), 1.0f);
        s1 += fminf(fmaxf(v1.x + bf, -1.0f), 1.0f) + fminf(fmaxf(v1.y + bf, -1.0f), 1.0f)
            + fminf(fmaxf(v1.z + bf, -1.0f), 1.0f) + fminf(fmaxf(v1.w + bf, -1.0f), 1.0f);
        s2 += fminf(fmaxf(v2.x + bf, -1.0f), 1.0f) + fminf(fmaxf(v2.y + bf, -1.0f), 1.0f)
            + fminf(fmaxf(v2.z + bf, -1.0f), 1.0f) + fminf(fmaxf(v2.w + bf, -1.0f), 1.0f);
        s3 += fminf(fmaxf(v3.x + bf, -1.0f), 1.0f) + fminf(fmaxf(v3.y + bf, -1.0f), 1.0f)
            + fminf(fmaxf(v3.z + bf, -1.0f), 1.0f) + fminf(fmaxf(v3.w + bf, -1.0f), 1.0f);
    }
    float s = (s0 + s1) + (s2 + s3);
    __shared__ float sh[256];
    sh[t] = s;
    __syncthreads();
    for (int o = 128; o > 0; o >>= 1) {
        if (t < o) sh[t] += sh[t + o];
        __syncthreads();
    }
    if (t == 0) g_part[blockIdx.x] = sh[0];
}

// ---------------------------------------------------------------------------
__global__ void mean_final()
{
    int i = threadIdx.x;
    if (i < Bb * Cc) {
        float s = 0.0f;
#pragma unroll
        for (int k = 0; k < PARTS; k++) s += g_part[i * PARTS + k];
        g_mean[i] = s * (1.0f / (float)NPIX);
    }
}

// ---------------------------------------------------------------------------
// Per-pixel color transform: brightness -> contrast -> HSV adjust -> RGB
// ---------------------------------------------------------------------------
__device__ __forceinline__ float3 color_xform(float cr, float cg, float cb,
                                              float bf, float cf,
                                              float mr, float mg, float mb2,
                                              float dh, float sf)
{
    cr = fminf(fmaxf(cr + bf, -1.0f), 1.0f);
    cg = fminf(fmaxf(cg + bf, -1.0f), 1.0f);
    cb = fminf(fmaxf(cb + bf, -1.0f), 1.0f);
    cr = fminf(fmaxf((cr - mr)  * cf + mr,  -1.0f), 1.0f);
    cg = fminf(fmaxf((cg - mg)  * cf + mg,  -1.0f), 1.0f);
    cb = fminf(fmaxf((cb - mb2) * cf + mb2, -1.0f), 1.0f);

    float mx = fmaxf(cr, fmaxf(cg, cb));
    float mn = fminf(cr, fminf(cg, cb));
    float d  = mx - mn;
    float invd = (d == 0.0f) ? 1.0f : __fdividef(1.0f, d);

    float tr = (cg - cb) * invd;
    float hr = tr * (1.0f / 6.0f);
    hr = (tr < 0.0f) ? hr + 1.0f : hr;
    float hg = fmaf((cb - cr) * invd, 1.0f / 6.0f, 2.0f / 6.0f);
    float hb = fmaf((cr - cg) * invd, 1.0f / 6.0f, 4.0f / 6.0f);
    float hch = (mx == cb) ? hb : ((mx == cg) ? hg : ((mx == cr) ? hr : 0.0f));

    float c = (mx > 0.0f) ? fminf(d * sf, mx) : 0.0f;
    float hp = fminf(fmaxf(hch + dh, 0.0f), 1.0f);

    float t6 = hp * 6.0f;
    float m2 = t6 - 2.0f * floorf(t6 * 0.5f);
    float xv = c * (1.0f - fabsf(m2 - 1.0f));
    float m  = mx - c;
    int seg  = (int)t6;
    float rr = (seg == 0 || seg == 5) ? c : ((seg == 1 || seg == 4) ? xv : 0.0f);
    float gg = (seg == 1 || seg == 2) ? c : ((seg == 0 || seg == 3) ? xv : 0.0f);
    float bb = (seg == 3 || seg == 4) ? c : ((seg == 2 || seg == 5) ? xv : 0.0f);
    return make_float3(rr + m, gg + m, bb + m);
}

// ---------------------------------------------------------------------------
// Kernel 2 v2: smem-tiled — transform each source pixel ONCE, then bilinear
// sample from smem. 64x64 output tile per block, 512 threads.
// ---------------------------------------------------------------------------
__global__ void __launch_bounds__(512, 2) aug_kernel(
    const float* __restrict__ img,
    const float* __restrict__ u_bright,
    const float* __restrict__ u_contrast,
    const float* __restrict__ u_hue,
    const float* __restrict__ u_sat,
    const float* __restrict__ u_angle,
    const float* __restrict__ noise,
    const int*   __restrict__ cutout_xy,
    const int*   __restrict__ cutout_apply,
    float*       __restrict__ out)
{
    extern __shared__ float sm[];   // [3][SPLANE]
    int b  = blockIdx.z;
    int w0 = blockIdx.x * TW;
    int h0 = blockIdx.y * TH;
    int t  = threadIdx.x;

    // Per-batch params
    float bf  = (u_bright[b]   * 2.0f - 1.0f) * 0.2f;
    float cf  = 1.0f + (u_contrast[b] * 2.0f - 1.0f) * 0.2f;
    float dh  = (u_hue[b]      * 2.0f - 1.0f) * 0.1f;
    float sf  = 1.0f + (u_sat[b]      * 2.0f - 1.0f) * 0.2f;
    float ang = (u_angle[b]    * 2.0f - 1.0f) * 0.17453292519943295f;
    float sa, ca;
    sincosf(ang, &sa, &ca);
    float mr  = g_mean[b * 3 + 0];
    float mg  = g_mean[b * 3 + 1];
    float mb2 = g_mean[b * 3 + 2];

    const float s2 = 2.0f / 511.0f;
    // Source bbox of this output tile (rotation is linear -> extremes at corners)
    float xxl = fmaf((float)w0,            s2, -1.0f);
    float xxh = fmaf((float)(w0 + TW - 1), s2, -1.0f);
    float yyl = fmaf((float)h0,            s2, -1.0f);
    float yyh = fmaf((float)(h0 + TH - 1), s2, -1.0f);

    float gx00 = ca * xxl - sa * yyl, gx01 = ca * xxh - sa * yyl;
    float gx10 = ca * xxl - sa * yyh, gx11 = ca * xxh - sa * yyh;
    float gy00 = sa * xxl + ca * yyl, gy01 = sa * xxh + ca * yyl;
    float gy10 = sa * xxl + ca * yyh, gy11 = sa * xxh + ca * yyh;

    float pxmin = fminf(fminf(gx00, gx01), fminf(gx10, gx11));
    float pxmax = fmaxf(fmaxf(gx00, gx01), fmaxf(gx10, gx11));
    float pymin = fminf(fminf(gy00, gy01), fminf(gy10, gy11));
    float pymax = fmaxf(fmaxf(gy00, gy01), fmaxf(gy10, gy11));

    int xs = (int)floorf((pxmin + 1.0f) * 256.0f - 0.5f);
    int xe = (int)floorf((pxmax + 1.0f) * 256.0f - 0.5f) + 1;
    int ys = (int)floorf((pymin + 1.0f) * 256.0f - 0.5f);
    int ye = (int)floorf((pymax + 1.0f) * 256.0f - 0.5f) + 1;
    int sw = xe - xs + 1; if (sw > SSTR) sw = SSTR;
    int sh = ye - ys + 1; if (sh > SSTR) sh = SSTR;

    // Load + transform source region into smem (transform ONCE per src pixel)
    const float* base = img + (size_t)b * Cc * NPIX;
    int total = sw * sh;
    for (int i = t; i < total; i += 512) {
        int ly = i / sw;
        int lx = i - ly * sw;
        int xi = xs + lx;
        int yi = ys + ly;
        if (xi >= 0 && xi < Ww && yi >= 0 && yi < Hh) {
            int off = (Hh - 1 - yi) * Ww + xi;   // vertical flip
            float r  = __ldg(base + off);
            float g  = __ldg(base + NPIX + off);
            float bl = __ldg(base + 2 * NPIX + off);
            float3 c = color_xform(r, g, bl, bf, cf, mr, mg, mb2, dh, sf);
            int si = ly * SSTR + lx;
            sm[si]              = c.x;
            sm[si + SPLANE]     = c.y;
            sm[si + 2 * SPLANE] = c.z;
        }
    }
    __syncthreads();

    // Sampling phase: 512 threads cover 64x64 outputs (8 px/thread)
    int tx = t & 31;        // 0..31
    int ty = t >> 5;        // 0..15

    int cx = cutout_xy[b * 2 + 0];
    int cy = cutout_xy[b * 2 + 1];
    bool apply = (cutout_apply[b] != 0);

#pragma unroll
    for (int dy = 0; dy < 4; dy++) {
#pragma unroll
        for (int dx = 0; dx < 2; dx++) {
            int w = w0 + tx + dx * 32;
            int h = h0 + ty + dy * 16;

            float xx = fmaf((float)w, s2, -1.0f);
            float yy = fmaf((float)h, s2, -1.0f);
            float gxp = (ca * xx - sa * yy + 1.0f) * 256.0f - 0.5f;
            float gyp = (sa * xx + ca * yy + 1.0f) * 256.0f - 0.5f;
            float x0f = floorf(gxp), y0f = floorf(gyp);
            float wx = gxp - x0f, wy = gyp - y0f;
            int x0 = (int)x0f, y0 = (int)y0f;

            float accr = 0.0f, accg = 0.0f, accb = 0.0f;
#pragma unroll
            for (int cyi = 0; cyi < 2; cyi++) {
                int yi = y0 + cyi;
                if (yi < 0 || yi >= Hh) continue;
                float wyc = cyi ? wy : (1.0f - wy);
                int srow = (yi - ys) * SSTR;
#pragma unroll
                for (int cxi = 0; cxi < 2; cxi++) {
                    int xi = x0 + cxi;
                    if (xi < 0 || xi >= Ww) continue;
                    float wgt = wyc * (cxi ? wx : (1.0f - wx));
                    int si = srow + (xi - xs);
                    accr = fmaf(sm[si],              wgt, accr);
                    accg = fmaf(sm[si + SPLANE],     wgt, accg);
                    accb = fmaf(sm[si + 2 * SPLANE], wgt, accb);
                }
            }

            size_t o = (size_t)b * Cc * NPIX + (size_t)h * Ww + w;
            float nr = noise[o];
            float ng = noise[o + NPIX];
            float nb = noise[o + 2 * NPIX];
            accr = fminf(fmaxf(fmaf(nr, 0.05f, accr), -1.0f), 1.0f);
            accg = fminf(fmaxf(fmaf(ng, 0.05f, accg), -1.0f), 1.0f);
            accb = fminf(fmaxf(fmaf(nb, 0.05f, accb), -1.0f), 1.0f);

            bool cut = apply && (h >= cy) && (h < cy + CUTSZ) &&
                               (w >= cx) && (w < cx + CUTSZ);
            if (cut) { accr = 0.0f; accg = 0.0f; accb = 0.0f; }

            out[o]            = accr;
            out[o + NPIX]     = accg;
            out[o + 2 * NPIX] = accb;
        }
    }
}

// ---------------------------------------------------------------------------
extern "C" void kernel_launch(void* const* d_in, const int* in_sizes, int n_in,
                              void* d_out, int out_size)
{
    const float* img        = (const float*)d_in[0];
    const float* u_bright   = (const float*)d_in[1];
    const float* u_contrast = (const float*)d_in[2];
    const float* u_hue      = (const float*)d_in[3];
    const float* u_sat      = (const float*)d_in[4];
    const float* u_angle    = (const float*)d_in[5];
    const float* noise      = (const float*)d_in[6];
    const int*   cutout_xy  = (const int*)d_in[7];
    const int*   cutout_ap  = (const int*)d_in[8];
    float* out = (float*)d_out;

    cudaFuncSetAttribute(aug_kernel, cudaFuncAttributeMaxDynamicSharedMemorySize, AUG_SMEM);

    mean_partial<<<Bb * Cc * PARTS, 256>>>(img, u_bright);
    mean_final<<<1, 128>>>();

    dim3 grd(Ww / TW, Hh / TH, Bb);
    aug_kernel<<<grd, 512, AUG_SMEM>>>(img, u_bright, u_contrast, u_hue, u_sat,
                                       u_angle, noise, cutout_xy, cutout_ap, out);
}